// round 1
// baseline (speedup 1.0000x reference)
#include <cuda_runtime.h>

#define IMG_H 128
#define IMG_W 128
#define PH 127
#define PW 127
#define NPATCH (PH * PW)      // 16129
#define BATCH 64
#define CHUNKS 8
#define TPB 256

// Coefficients computed once per launch by setup_kernel.
__device__ float g_qc[6];     // quadratic-form coeffs, pre-scaled by head_w[1]
__device__ float g_cw[4];     // conv weights, pre-scaled by head_w[0]
__device__ float g_const;     // head_w[0]*conv_b + head_b
__device__ float g_partial[BATCH * CHUNKS];

// Build U = C * R1 * C * R0 (4x4 real, qubits 0,1), then M = U^T Z0 U.
// Fold head weights into the 6 needed quadratic coefficients.
__global__ void setup_kernel(const float* __restrict__ conv_w,
                             const float* __restrict__ conv_b,
                             const float* __restrict__ ry,      // (2,4) row-major
                             const float* __restrict__ head_w,  // (1,2)
                             const float* __restrict__ head_b) {
    if (threadIdx.x != 0 || blockIdx.x != 0) return;

    float U[4][4];
    for (int i = 0; i < 4; i++)
        for (int j = 0; j < 4; j++)
            U[i][j] = (i == j) ? 1.0f : 0.0f;

    for (int l = 0; l < 2; l++) {
        float c0 = cosf(0.5f * ry[l * 4 + 0]);
        float s0 = sinf(0.5f * ry[l * 4 + 0]);
        float c1 = cosf(0.5f * ry[l * 4 + 1]);
        float s1 = sinf(0.5f * ry[l * 4 + 1]);
        float A[2][2] = {{c0, -s0}, {s0, c0}};   // RY on q0
        float Bm[2][2] = {{c1, -s1}, {s1, c1}};  // RY on q1
        float R[4][4];
        for (int i = 0; i < 4; i++)
            for (int j = 0; j < 4; j++)
                R[i][j] = A[i >> 1][j >> 1] * Bm[i & 1][j & 1];
        // T = R @ U
        float T[4][4];
        for (int i = 0; i < 4; i++)
            for (int j = 0; j < 4; j++) {
                float s = 0.0f;
                for (int k = 0; k < 4; k++) s += R[i][k] * U[k][j];
                T[i][j] = s;
            }
        // Apply CNOT(ctrl=0, tgt=1): swap rows 2 and 3 (state index i = q0*2+q1)
        for (int j = 0; j < 4; j++) {
            U[0][j] = T[0][j];
            U[1][j] = T[1][j];
            U[2][j] = T[3][j];
            U[3][j] = T[2][j];
        }
    }

    // M[j][k] = sum_i z_i * U[i][j] * U[i][k], z = (+1,+1,-1,-1)
    float M00 = 0, M03 = 0, M33 = 0, M11 = 0, M12 = 0, M22 = 0;
    for (int i = 0; i < 4; i++) {
        float z = (i < 2) ? 1.0f : -1.0f;
        M00 += z * U[i][0] * U[i][0];
        M03 += z * U[i][0] * U[i][3];
        M33 += z * U[i][3] * U[i][3];
        M11 += z * U[i][1] * U[i][1];
        M12 += z * U[i][1] * U[i][2];
        M22 += z * U[i][2] * U[i][2];
    }

    float hw0 = head_w[0];
    float hw1 = head_w[1];
    // v_r = (cc, 0, 0, -ss): q_r = M00*cc^2 - 2*M03*cc*ss + M33*ss^2
    // v_i = (0, -cs, -sc, 0): q_i = M11*cs^2 + 2*M12*cs*sc + M22*sc^2
    g_qc[0] = hw1 * M00;
    g_qc[1] = hw1 * (-2.0f * M03);
    g_qc[2] = hw1 * M33;
    g_qc[3] = hw1 * M11;
    g_qc[4] = hw1 * (2.0f * M12);
    g_qc[5] = hw1 * M22;
    for (int i = 0; i < 4; i++) g_cw[i] = hw0 * conv_w[i];
    g_const = hw0 * conv_b[0] + head_b[0];
}

__global__ void __launch_bounds__(TPB) patch_kernel(const float* __restrict__ x) {
    const int b = blockIdx.y;
    const int chunk = blockIdx.x;
    const float* __restrict__ img = x + (size_t)b * IMG_H * IMG_W;

    const float q0 = g_qc[0], q1 = g_qc[1], q2 = g_qc[2];
    const float q3 = g_qc[3], q4 = g_qc[4], q5 = g_qc[5];
    const float w0 = g_cw[0], w1 = g_cw[1], w2 = g_cw[2], w3 = g_cw[3];

    const int per = (NPATCH + CHUNKS - 1) / CHUNKS;  // 2017
    const int start = chunk * per;
    const int end = (start + per < NPATCH) ? (start + per) : NPATCH;

    float acc = 0.0f;
    for (int i = start + threadIdx.x; i < end; i += TPB) {
        int ph = i / PW;
        int pw = i - ph * PW;
        const float* r0 = img + ph * IMG_W + pw;
        float a0 = r0[0];
        float a1 = r0[1];
        float a2 = r0[IMG_W];
        float a3 = r0[IMG_W + 1];

        float s0, c0, s1, c1;
        __sincosf(0.5f * a0, &s0, &c0);
        __sincosf(0.5f * a1, &s1, &c1);

        float cc = c0 * c1, ss = s0 * s1, cs = c0 * s1, sc = s0 * c1;
        float q = q0 * cc * cc + q1 * cc * ss + q2 * ss * ss +
                  q3 * cs * cs + q4 * cs * sc + q5 * sc * sc;
        float conv = w0 * a0 + w1 * a1 + w2 * a2 + w3 * a3;
        acc += q + conv;
    }

    // Deterministic block reduction: warp shuffle + shared
    __shared__ float sh[TPB / 32];
    unsigned m = 0xFFFFFFFFu;
    acc += __shfl_down_sync(m, acc, 16);
    acc += __shfl_down_sync(m, acc, 8);
    acc += __shfl_down_sync(m, acc, 4);
    acc += __shfl_down_sync(m, acc, 2);
    acc += __shfl_down_sync(m, acc, 1);
    int lane = threadIdx.x & 31;
    int wid = threadIdx.x >> 5;
    if (lane == 0) sh[wid] = acc;
    __syncthreads();
    if (wid == 0) {
        float v = (lane < TPB / 32) ? sh[lane] : 0.0f;
        v += __shfl_down_sync(m, v, 4);
        v += __shfl_down_sync(m, v, 2);
        v += __shfl_down_sync(m, v, 1);
        if (lane == 0) g_partial[b * CHUNKS + chunk] = v;
    }
}

__global__ void finish_kernel(float* __restrict__ out) {
    int b = threadIdx.x;
    if (b < BATCH) {
        float s = 0.0f;
        for (int c = 0; c < CHUNKS; c++) s += g_partial[b * CHUNKS + c];
        out[b] = s * (1.0f / (float)NPATCH) + g_const;
    }
}

extern "C" void kernel_launch(void* const* d_in, const int* in_sizes, int n_in,
                              void* d_out, int out_size) {
    const float* x      = (const float*)d_in[0];
    const float* conv_w = (const float*)d_in[1];
    const float* conv_b = (const float*)d_in[2];
    const float* ry     = (const float*)d_in[3];
    const float* head_w = (const float*)d_in[4];
    const float* head_b = (const float*)d_in[5];
    float* out = (float*)d_out;

    setup_kernel<<<1, 32>>>(conv_w, conv_b, ry, head_w, head_b);
    dim3 grid(CHUNKS, BATCH);
    patch_kernel<<<grid, TPB>>>(x);
    finish_kernel<<<1, 64>>>(out);
}

// round 2
// speedup vs baseline: 1.0248x; 1.0248x over previous
#include <cuda_runtime.h>

#define BATCH   64
#define CHUNKS  8
#define NBLOCKS (BATCH * CHUNKS)   // 512
#define TPB     256
#define PW      127
#define PH      127
#define NPATCH  (PH * PW)          // 16129
#define NPIX    (PH * 128)         // 16256 iteration space (skip pw==127)

__device__ float g_partial[NBLOCKS];
__device__ unsigned int g_count = 0;

__global__ void __launch_bounds__(TPB) fused_kernel(
    const float* __restrict__ x,
    const float* __restrict__ conv_w,
    const float* __restrict__ conv_b,
    const float* __restrict__ ry,      // (2,4)
    const float* __restrict__ head_w,  // (1,2)
    const float* __restrict__ head_b,
    float* __restrict__ out)
{
    __shared__ float coef[11];   // q0..q5, w0..w3, const
    __shared__ float wsum[TPB / 32];
    __shared__ bool  s_last;

    // ---- per-block coefficient computation (thread 0) ----
    if (threadIdx.x == 0) {
        float U[4][4] = {{1,0,0,0},{0,1,0,0},{0,0,1,0},{0,0,0,1}};
        for (int l = 0; l < 2; l++) {
            float c0, s0, c1, s1;
            __sincosf(0.5f * ry[l * 4 + 0], &s0, &c0);
            __sincosf(0.5f * ry[l * 4 + 1], &s1, &c1);
            float A[2][2]  = {{c0, -s0}, {s0, c0}};   // RY q0
            float Bm[2][2] = {{c1, -s1}, {s1, c1}};   // RY q1
            float T[4][4];
            for (int i = 0; i < 4; i++)
                for (int j = 0; j < 4; j++) {
                    float s = 0.0f;
                    for (int k = 0; k < 4; k++)
                        s += A[i >> 1][k >> 1] * Bm[i & 1][k & 1] * U[k][j];
                    T[i][j] = s;
                }
            // CNOT(0,1): swap rows 2,3
            for (int j = 0; j < 4; j++) {
                U[0][j] = T[0][j]; U[1][j] = T[1][j];
                U[2][j] = T[3][j]; U[3][j] = T[2][j];
            }
        }
        float M00 = 0, M03 = 0, M33 = 0, M11 = 0, M12 = 0, M22 = 0;
        for (int i = 0; i < 4; i++) {
            float z = (i < 2) ? 1.0f : -1.0f;
            M00 += z * U[i][0] * U[i][0];
            M03 += z * U[i][0] * U[i][3];
            M33 += z * U[i][3] * U[i][3];
            M11 += z * U[i][1] * U[i][1];
            M12 += z * U[i][1] * U[i][2];
            M22 += z * U[i][2] * U[i][2];
        }
        float hw0 = head_w[0];
        float hw1 = head_w[1];
        coef[0] = hw1 * M00;
        coef[1] = hw1 * (-2.0f * M03);
        coef[2] = hw1 * M33;
        coef[3] = hw1 * M11;
        coef[4] = hw1 * (2.0f * M12);
        coef[5] = hw1 * M22;
        coef[6] = hw0 * conv_w[0];
        coef[7] = hw0 * conv_w[1];
        coef[8] = hw0 * conv_w[2];
        coef[9] = hw0 * conv_w[3];
        coef[10] = hw0 * conv_b[0] + head_b[0];
    }
    __syncthreads();

    const float q0 = coef[0], q1 = coef[1], q2 = coef[2];
    const float q3 = coef[3], q4 = coef[4], q5 = coef[5];
    const float w0 = coef[6], w1 = coef[7], w2 = coef[8], w3 = coef[9];

    // ---- patch loop over pixel space ----
    const int b     = blockIdx.x >> 3;
    const int chunk = blockIdx.x & 7;
    const float* __restrict__ img = x + (size_t)b * 16384;

    const int per   = (NPIX + CHUNKS - 1) / CHUNKS;  // 2032
    const int start = chunk * per;
    const int end   = (start + per < NPIX) ? (start + per) : NPIX;

    float acc = 0.0f;
    for (int idx = start + threadIdx.x; idx < end; idx += TPB) {
        int pw = idx & 127;
        if (pw != 127) {
            float a0 = img[idx];
            float a1 = img[idx + 1];
            float a2 = img[idx + 128];
            float a3 = img[idx + 129];

            float s0, c0, s1, c1;
            __sincosf(0.5f * a0, &s0, &c0);
            __sincosf(0.5f * a1, &s1, &c1);

            float cc = c0 * c1, ss = s0 * s1, cs = c0 * s1, sc = s0 * c1;
            float q = q0 * cc * cc + q1 * cc * ss + q2 * ss * ss +
                      q3 * cs * cs + q4 * cs * sc + q5 * sc * sc;
            float conv = w0 * a0 + w1 * a1 + w2 * a2 + w3 * a3;
            acc += q + conv;
        }
    }

    // ---- block reduction (deterministic) ----
    unsigned m = 0xFFFFFFFFu;
    acc += __shfl_down_sync(m, acc, 16);
    acc += __shfl_down_sync(m, acc, 8);
    acc += __shfl_down_sync(m, acc, 4);
    acc += __shfl_down_sync(m, acc, 2);
    acc += __shfl_down_sync(m, acc, 1);
    int lane = threadIdx.x & 31;
    int wid  = threadIdx.x >> 5;
    if (lane == 0) wsum[wid] = acc;
    __syncthreads();
    if (threadIdx.x == 0) {
        float v = wsum[0];
        for (int w = 1; w < TPB / 32; w++) v += wsum[w];
        g_partial[blockIdx.x] = v;
        __threadfence();
        unsigned done = atomicAdd(&g_count, 1u);
        s_last = (done == NBLOCKS - 1);
    }
    __syncthreads();

    // ---- last block finalizes (fixed summation order -> deterministic) ----
    if (s_last) {
        int t = threadIdx.x;
        if (t < BATCH) {
            float s = 0.0f;
            for (int c = 0; c < CHUNKS; c++)
                s += __ldcg(&g_partial[t * CHUNKS + c]);
            out[t] = s * (1.0f / (float)NPATCH) + coef[10];
        }
        __syncthreads();
        if (threadIdx.x == 0) g_count = 0;   // reset for next graph replay
    }
}

extern "C" void kernel_launch(void* const* d_in, const int* in_sizes, int n_in,
                              void* d_out, int out_size) {
    const float* x      = (const float*)d_in[0];
    const float* conv_w = (const float*)d_in[1];
    const float* conv_b = (const float*)d_in[2];
    const float* ry     = (const float*)d_in[3];
    const float* head_w = (const float*)d_in[4];
    const float* head_b = (const float*)d_in[5];
    float* out = (float*)d_out;

    fused_kernel<<<NBLOCKS, TPB>>>(x, conv_w, conv_b, ry, head_w, head_b, out);
}